// round 12
// baseline (speedup 1.0000x reference)
#include <cuda_runtime.h>
#include <cuda_fp16.h>
#include <cstdint>
#include <math.h>

#define L_DENSE 1024
#define LT      64
#define NSTEPS  64        // K / 16
#define MTILE   128       // rows per CTA (8 warps x 16)
#define THREADS 256

// W fragments, PERMUTED k-layout (lane c holds k = 4c..4c+3 within each k16 step),
// n-tiles paired into uint4 for LDG.128:
// g_Bfrag4[ks*128 + np*32 + lane] = { h2(W[na][k0],W[na][k0+1]), h2(W[na][k0+2],W[na][k0+3]),
//                                     h2(W[nb][k0],W[nb][k0+1]), h2(W[nb][k0+2],W[nb][k0+3]) }
// na = 16np + lane/4, nb = na + 8, k0 = ks*16 + (lane%4)*4
__device__ uint4 g_Bfrag4[NSTEPS * 4 * 32];

static __device__ __forceinline__ uint32_t f2_h2(float lo, float hi) {
    uint32_t u;
    asm("cvt.rn.f16x2.f32 %0, %1, %2;" : "=r"(u) : "f"(hi), "f"(lo));
    return u;
}

__global__ void precompute_frag(const float* __restrict__ weight) {
    int ks   = blockIdx.x;           // 0..63
    int np   = threadIdx.x >> 5;     // 0..3
    int lane = threadIdx.x & 31;
    int na = np * 16 + (lane >> 2);
    int nb = na + 8;
    int k0 = ks * 16 + (lane & 3) * 4;
    float wa = weight[na], wb = weight[nb];
    uint4 v;
    {
        float d0 = (float)(k0 + 1) - wa, d1 = (float)(k0 + 2) - wa;
        float d2 = (float)(k0 + 3) - wa, d3 = (float)(k0 + 4) - wa;
        v.x = f2_h2(expf(-d0 * d0 * 0.01f), expf(-d1 * d1 * 0.01f));
        v.y = f2_h2(expf(-d2 * d2 * 0.01f), expf(-d3 * d3 * 0.01f));
    }
    {
        float d0 = (float)(k0 + 1) - wb, d1 = (float)(k0 + 2) - wb;
        float d2 = (float)(k0 + 3) - wb, d3 = (float)(k0 + 4) - wb;
        v.z = f2_h2(expf(-d0 * d0 * 0.01f), expf(-d1 * d1 * 0.01f));
        v.w = f2_h2(expf(-d2 * d2 * 0.01f), expf(-d3 * d3 * 0.01f));
    }
    g_Bfrag4[ks * 128 + np * 32 + lane] = v;
}

static __device__ __forceinline__ void mma16816(float c[4],
        uint32_t a0, uint32_t a1, uint32_t a2, uint32_t a3,
        uint32_t b0, uint32_t b1) {
    asm volatile(
        "mma.sync.aligned.m16n8k16.row.col.f32.f16.f16.f32 "
        "{%0,%1,%2,%3}, {%4,%5,%6,%7}, {%8,%9}, {%0,%1,%2,%3};"
        : "+f"(c[0]), "+f"(c[1]), "+f"(c[2]), "+f"(c[3])
        : "r"(a0), "r"(a1), "r"(a2), "r"(a3), "r"(b0), "r"(b1));
}

__global__ void __launch_bounds__(THREADS, 3)
gemm_hmma(const float* __restrict__ x, float* __restrict__ out, int rows)
{
    const int tid  = threadIdx.x;
    const int warp = tid >> 5;
    const int lane = tid & 31;
    const int r0   = blockIdx.x * MTILE + warp * 16;   // this warp's first row (m16)
    const int rq   = lane >> 2;                        // row within 8-group
    const int kq   = (lane & 3) * 4;                   // permuted k quad base
    const int cc   = (lane & 3) * 2;                   // C column pair (layout fixed)

    const float* xw = x + (size_t)r0 * L_DENSE;

    float c[8][4];
    #pragma unroll
    for (int nt = 0; nt < 8; ++nt)
        #pragma unroll
        for (int q = 0; q < 4; ++q) c[nt][q] = 0.f;

    uint32_t a[4];

    // A: 2 LDG.128 per k-step (rows rq and rq+8); permuted slots: a0/a2 = low
    // quad pairs of row rq, a1/a3 = of row rq+8.
    auto loadA = [&](int ks, uint32_t dst[4]) {
        const float4* p = (const float4*)(xw + (size_t)rq * L_DENSE + ks * 16 + kq);
        float4 v0 = __ldcs(p);
        float4 v1 = __ldcs(p + 2 * L_DENSE);   // +8 rows (8*1024 floats = 2048 float4)
        dst[0] = f2_h2(v0.x, v0.y);
        dst[2] = f2_h2(v0.z, v0.w);
        dst[1] = f2_h2(v1.x, v1.y);
        dst[3] = f2_h2(v1.z, v1.w);
    };

    loadA(0, a);

    #pragma unroll 2
    for (int ks = 0; ks < NSTEPS; ++ks) {
        uint32_t an[4];
        if (ks + 1 < NSTEPS) loadA(ks + 1, an);

        // B: L1-hot (shared table), loaded in-step, no prefetch registers
        const uint4* bp = g_Bfrag4 + ks * 128 + lane;
        #pragma unroll
        for (int np = 0; np < 4; ++np) {
            uint4 bv = bp[np * 32];
            mma16816(c[2 * np + 0], a[0], a[1], a[2], a[3], bv.x, bv.y);
            mma16816(c[2 * np + 1], a[0], a[1], a[2], a[3], bv.z, bv.w);
        }

        if (ks + 1 < NSTEPS) {
            #pragma unroll
            for (int q = 0; q < 4; ++q) a[q] = an[q];
        }
    }

    // ---- epilogue: C layout: (rq, 2c..2c+1) and (rq+8, ...) ----
    {
        int r = r0 + rq;
        #pragma unroll
        for (int nt = 0; nt < 8; ++nt) {
            if (r < rows) {
                float2 v; v.x = c[nt][0]; v.y = c[nt][1];
                __stcs((float2*)(out + (size_t)r * LT + nt * 8 + cc), v);
            }
            if (r + 8 < rows) {
                float2 w; w.x = c[nt][2]; w.y = c[nt][3];
                __stcs((float2*)(out + (size_t)(r + 8) * LT + nt * 8 + cc), w);
            }
        }
    }
}

extern "C" void kernel_launch(void* const* d_in, const int* in_sizes, int n_in,
                              void* d_out, int out_size) {
    const float* x      = (const float*)d_in[0];
    const float* weight = (const float*)d_in[1];
    float* out          = (float*)d_out;

    const int rows = in_sizes[0] / L_DENSE;   // 131072

    precompute_frag<<<NSTEPS, 128>>>(weight);
    gemm_hmma<<<(rows + MTILE - 1) / MTILE, THREADS>>>(x, out, rows);
}

// round 13
// speedup vs baseline: 1.0388x; 1.0388x over previous
#include <cuda_runtime.h>
#include <cuda_fp16.h>
#include <cstdint>
#include <math.h>

#define L_DENSE 1024
#define LT      64
#define NSTEPS  64        // K / 16
#define MTILE   128       // rows per CTA (8 warps x 16)
#define THREADS 256
#define STAGES  8
#define STAGE_FLOATS (MTILE * 16)   // 2048 floats = 8KB per stage

// W fragments, PERMUTED k-layout (lane c holds k = 4c..4c+3 within each k16 step),
// n-tiles paired into uint4 for LDG.128 (see round-10 notes).
__device__ uint4 g_Bfrag4[NSTEPS * 4 * 32];

static __device__ __forceinline__ uint32_t f2_h2(float lo, float hi) {
    uint32_t u;
    asm("cvt.rn.f16x2.f32 %0, %1, %2;" : "=r"(u) : "f"(hi), "f"(lo));
    return u;
}

__global__ void precompute_frag(const float* __restrict__ weight) {
    int ks   = blockIdx.x;           // 0..63
    int np   = threadIdx.x >> 5;     // 0..3
    int lane = threadIdx.x & 31;
    int na = np * 16 + (lane >> 2);
    int nb = na + 8;
    int k0 = ks * 16 + (lane & 3) * 4;
    float wa = weight[na], wb = weight[nb];
    uint4 v;
    {
        float d0 = (float)(k0 + 1) - wa, d1 = (float)(k0 + 2) - wa;
        float d2 = (float)(k0 + 3) - wa, d3 = (float)(k0 + 4) - wa;
        v.x = f2_h2(expf(-d0 * d0 * 0.01f), expf(-d1 * d1 * 0.01f));
        v.y = f2_h2(expf(-d2 * d2 * 0.01f), expf(-d3 * d3 * 0.01f));
    }
    {
        float d0 = (float)(k0 + 1) - wb, d1 = (float)(k0 + 2) - wb;
        float d2 = (float)(k0 + 3) - wb, d3 = (float)(k0 + 4) - wb;
        v.z = f2_h2(expf(-d0 * d0 * 0.01f), expf(-d1 * d1 * 0.01f));
        v.w = f2_h2(expf(-d2 * d2 * 0.01f), expf(-d3 * d3 * 0.01f));
    }
    g_Bfrag4[ks * 128 + np * 32 + lane] = v;
}

static __device__ __forceinline__ void mma16816(float c[4],
        uint32_t a0, uint32_t a1, uint32_t a2, uint32_t a3,
        uint32_t b0, uint32_t b1) {
    asm volatile(
        "mma.sync.aligned.m16n8k16.row.col.f32.f16.f16.f32 "
        "{%0,%1,%2,%3}, {%4,%5,%6,%7}, {%8,%9}, {%0,%1,%2,%3};"
        : "+f"(c[0]), "+f"(c[1]), "+f"(c[2]), "+f"(c[3])
        : "r"(a0), "r"(a1), "r"(a2), "r"(a3), "r"(b0), "r"(b1));
}

static __device__ __forceinline__ uint32_t smem_u32(const void* p) {
    uint32_t a;
    asm("{ .reg .u64 t; cvta.to.shared.u64 t, %1; cvt.u32.u64 %0, t; }" : "=r"(a) : "l"(p));
    return a;
}
static __device__ __forceinline__ void cp16(uint32_t saddr, const void* gaddr) {
    asm volatile("cp.async.cg.shared.global [%0], [%1], 16;" :: "r"(saddr), "l"(gaddr));
}
#define CP_COMMIT()  asm volatile("cp.async.commit_group;" ::: "memory")
#define CP_WAIT6()   asm volatile("cp.async.wait_group 6;" ::: "memory")

__global__ void __launch_bounds__(THREADS, 3)
gemm_hmma(const float* __restrict__ x, float* __restrict__ out, int rows)
{
    extern __shared__ float SA[];   // STAGES * 2048 floats = 64 KB

    const int tid  = threadIdx.x;
    const int warp = tid >> 5;
    const int lane = tid & 31;
    const int r0   = blockIdx.x * MTILE;
    const int wr0  = r0 + warp * 16;                   // warp's first row (m16)
    const int rq   = lane >> 2;                        // row within 8-group
    const int kq   = (lane & 3) * 4;                   // permuted k quad base
    const int cc   = (lane & 3) * 2;                   // C column pair

    // staging map: 512 x 16B chunks per stage; thread t -> chunks t, t+256
    const int srow0 = tid >> 2;            // rows 0..63 (chunk t)
    const int sseg0 = tid & 3;
    const uint32_t sbase = smem_u32(SA);

    auto issue_stage = [&](int ks) {
        const float* g0 = x + (size_t)(r0 + srow0) * L_DENSE + ks * 16 + sseg0 * 4;
        uint32_t s0 = sbase + (((ks & (STAGES - 1)) * STAGE_FLOATS
                                + srow0 * 16 + sseg0 * 4) << 2);
        cp16(s0, g0);
        cp16(s0 + (64 * 16 << 2), g0 + (size_t)64 * L_DENSE);   // chunk t+256 -> rows 64..127
    };

    // prologue: fill STAGES-1 stages
    #pragma unroll
    for (int s = 0; s < STAGES - 1; ++s) { issue_stage(s); CP_COMMIT(); }

    float c[8][4];
    #pragma unroll
    for (int nt = 0; nt < 8; ++nt)
        #pragma unroll
        for (int q = 0; q < 4; ++q) c[nt][q] = 0.f;

    const float* aw0 = SA + (warp * 16 + rq) * 16 + kq;   // within-stage offset

    for (int ks = 0; ks < NSTEPS; ++ks) {
        CP_WAIT6();
        __syncthreads();

        // refill: overwrite the stage consumed STAGES-1 steps ago
        if (ks + STAGES - 1 < NSTEPS) issue_stage(ks + STAGES - 1);
        CP_COMMIT();   // unconditional: keeps wait_group count aligned at the tail

        // A fragment from smem: conflict-free LDS.128 x2
        const float* ap = aw0 + (ks & (STAGES - 1)) * STAGE_FLOATS;
        float4 v0 = *(const float4*)(ap);
        float4 v1 = *(const float4*)(ap + 8 * 16);
        uint32_t a0 = f2_h2(v0.x, v0.y);
        uint32_t a2 = f2_h2(v0.z, v0.w);
        uint32_t a1 = f2_h2(v1.x, v1.y);
        uint32_t a3 = f2_h2(v1.z, v1.w);

        // B: L1-hot fragment table
        const uint4* bp = g_Bfrag4 + ks * 128 + lane;
        #pragma unroll
        for (int np = 0; np < 4; ++np) {
            uint4 bv = bp[np * 32];
            mma16816(c[2 * np + 0], a0, a1, a2, a3, bv.x, bv.y);
            mma16816(c[2 * np + 1], a0, a1, a2, a3, bv.z, bv.w);
        }
        __syncthreads();
    }

    // ---- epilogue: C layout: (rq, 2c..2c+1) and (rq+8, ...) ----
    {
        int r = wr0 + rq;
        #pragma unroll
        for (int nt = 0; nt < 8; ++nt) {
            if (r < rows) {
                float2 v; v.x = c[nt][0]; v.y = c[nt][1];
                __stcs((float2*)(out + (size_t)r * LT + nt * 8 + cc), v);
            }
            if (r + 8 < rows) {
                float2 w; w.x = c[nt][2]; w.y = c[nt][3];
                __stcs((float2*)(out + (size_t)(r + 8) * LT + nt * 8 + cc), w);
            }
        }
    }
}

extern "C" void kernel_launch(void* const* d_in, const int* in_sizes, int n_in,
                              void* d_out, int out_size) {
    const float* x      = (const float*)d_in[0];
    const float* weight = (const float*)d_in[1];
    float* out          = (float*)d_out;

    const int rows = in_sizes[0] / L_DENSE;   // 131072
    const int smem = STAGES * STAGE_FLOATS * 4;   // 64 KB

    cudaFuncSetAttribute(gemm_hmma, cudaFuncAttributeMaxDynamicSharedMemorySize, smem);

    precompute_frag<<<NSTEPS, 128>>>(weight);
    gemm_hmma<<<(rows + MTILE - 1) / MTILE, THREADS, smem>>>(x, out, rows);
}

// round 14
// speedup vs baseline: 1.1385x; 1.0960x over previous
#include <cuda_runtime.h>
#include <cuda_fp16.h>
#include <cstdint>
#include <math.h>

#define L_DENSE 1024
#define LT      64
#define NSTEPS  64        // K / 16
#define MTILE   128       // rows per CTA (8 warps x 16)
#define THREADS 256
#define STAGES  4         // per-warp ring: 4 x 1KB

// W fragments, PERMUTED k-layout (lane c holds k = 4c..4c+3 within each k16 step),
// n-tiles paired into uint4 for LDG.128 (see round-10 notes).
__device__ uint4 g_Bfrag4[NSTEPS * 4 * 32];

static __device__ __forceinline__ uint32_t f2_h2(float lo, float hi) {
    uint32_t u;
    asm("cvt.rn.f16x2.f32 %0, %1, %2;" : "=r"(u) : "f"(hi), "f"(lo));
    return u;
}

__global__ void precompute_frag(const float* __restrict__ weight) {
    int ks   = blockIdx.x;           // 0..63
    int np   = threadIdx.x >> 5;     // 0..3
    int lane = threadIdx.x & 31;
    int na = np * 16 + (lane >> 2);
    int nb = na + 8;
    int k0 = ks * 16 + (lane & 3) * 4;
    float wa = weight[na], wb = weight[nb];
    uint4 v;
    {
        float d0 = (float)(k0 + 1) - wa, d1 = (float)(k0 + 2) - wa;
        float d2 = (float)(k0 + 3) - wa, d3 = (float)(k0 + 4) - wa;
        v.x = f2_h2(expf(-d0 * d0 * 0.01f), expf(-d1 * d1 * 0.01f));
        v.y = f2_h2(expf(-d2 * d2 * 0.01f), expf(-d3 * d3 * 0.01f));
    }
    {
        float d0 = (float)(k0 + 1) - wb, d1 = (float)(k0 + 2) - wb;
        float d2 = (float)(k0 + 3) - wb, d3 = (float)(k0 + 4) - wb;
        v.z = f2_h2(expf(-d0 * d0 * 0.01f), expf(-d1 * d1 * 0.01f));
        v.w = f2_h2(expf(-d2 * d2 * 0.01f), expf(-d3 * d3 * 0.01f));
    }
    g_Bfrag4[ks * 128 + np * 32 + lane] = v;
}

static __device__ __forceinline__ void mma16816(float c[4],
        uint32_t a0, uint32_t a1, uint32_t a2, uint32_t a3,
        uint32_t b0, uint32_t b1) {
    asm volatile(
        "mma.sync.aligned.m16n8k16.row.col.f32.f16.f16.f32 "
        "{%0,%1,%2,%3}, {%4,%5,%6,%7}, {%8,%9}, {%0,%1,%2,%3};"
        : "+f"(c[0]), "+f"(c[1]), "+f"(c[2]), "+f"(c[3])
        : "r"(a0), "r"(a1), "r"(a2), "r"(a3), "r"(b0), "r"(b1));
}

static __device__ __forceinline__ uint32_t smem_u32(const void* p) {
    uint32_t a;
    asm("{ .reg .u64 t; cvta.to.shared.u64 t, %1; cvt.u32.u64 %0, t; }" : "=r"(a) : "l"(p));
    return a;
}
static __device__ __forceinline__ void cp16(uint32_t saddr, const void* gaddr) {
    asm volatile("cp.async.cg.shared.global [%0], [%1], 16;" :: "r"(saddr), "l"(gaddr));
}
#define CP_COMMIT()  asm volatile("cp.async.commit_group;" ::: "memory")
#define CP_WAIT2()   asm volatile("cp.async.wait_group 2;" ::: "memory")

__global__ void __launch_bounds__(THREADS, 3)
gemm_hmma(const float* __restrict__ x, float* __restrict__ out, int rows)
{
    // 8 warps x 4 stages x 1KB = 32KB static smem (3 CTAs/SM -> 96KB, L1D = 132KB)
    __shared__ __align__(16) float SA[8 * STAGES * 256];

    const int tid  = threadIdx.x;
    const int warp = tid >> 5;
    const int lane = tid & 31;
    const int wr0  = blockIdx.x * MTILE + warp * 16;   // warp's first row (m16)
    const int rq   = lane >> 2;                        // row within 8-group
    const int kq   = (lane & 3) * 4;                   // permuted k quad base
    const int cc   = (lane & 3) * 2;                   // C column pair

    // Per-warp private staging. Lane l writes 16B chunks l (row rq) and l+32
    // (row rq+8) of the stage; the MMA read of lane l touches EXACTLY those
    // chunks -> per-thread cp.async visibility suffices, NO barriers anywhere.
    const float*   gbase  = x + (size_t)(wr0 + rq) * L_DENSE + kq;
    const uint32_t swbase = smem_u32(SA) + warp * (STAGES * 1024) + lane * 16;

    auto issue_stage = [&](int ks) {
        uint32_t s = swbase + (ks & (STAGES - 1)) * 1024;
        const float* g = gbase + ks * 16;
        cp16(s,       g);
        cp16(s + 512, g + 8 * L_DENSE);
    };

    // prologue: fill STAGES-1 stages
    #pragma unroll
    for (int s = 0; s < STAGES - 1; ++s) { issue_stage(s); CP_COMMIT(); }

    float c[8][4];
    #pragma unroll
    for (int nt = 0; nt < 8; ++nt)
        #pragma unroll
        for (int q = 0; q < 4; ++q) c[nt][q] = 0.f;

    const float* aw0 = SA + warp * (STAGES * 256) + rq * 16 + kq;

    #pragma unroll 4
    for (int ks = 0; ks < NSTEPS; ++ks) {
        CP_WAIT2();

        if (ks + STAGES - 1 < NSTEPS) issue_stage(ks + STAGES - 1);
        CP_COMMIT();   // unconditional: keeps wait_group count aligned at the tail

        // A fragment from own-written smem chunks: 2x LDS.128, conflict-free
        const float* ap = aw0 + (ks & (STAGES - 1)) * 256;
        float4 v0 = *(const float4*)(ap);
        float4 v1 = *(const float4*)(ap + 128);
        uint32_t a0 = f2_h2(v0.x, v0.y);
        uint32_t a2 = f2_h2(v0.z, v0.w);
        uint32_t a1 = f2_h2(v1.x, v1.y);
        uint32_t a3 = f2_h2(v1.z, v1.w);

        // B: L1-resident fragment table (fits the 132KB carveout again)
        const uint4* bp = g_Bfrag4 + ks * 128 + lane;
        #pragma unroll
        for (int np = 0; np < 4; ++np) {
            uint4 bv = bp[np * 32];
            mma16816(c[2 * np + 0], a0, a1, a2, a3, bv.x, bv.y);
            mma16816(c[2 * np + 1], a0, a1, a2, a3, bv.z, bv.w);
        }
    }

    // ---- epilogue: C layout: (rq, 2c..2c+1) and (rq+8, ...) ----
    {
        int r = wr0 + rq;
        #pragma unroll
        for (int nt = 0; nt < 8; ++nt) {
            if (r < rows) {
                float2 v; v.x = c[nt][0]; v.y = c[nt][1];
                __stcs((float2*)(out + (size_t)r * LT + nt * 8 + cc), v);
            }
            if (r + 8 < rows) {
                float2 w; w.x = c[nt][2]; w.y = c[nt][3];
                __stcs((float2*)(out + (size_t)(r + 8) * LT + nt * 8 + cc), w);
            }
        }
    }
}

extern "C" void kernel_launch(void* const* d_in, const int* in_sizes, int n_in,
                              void* d_out, int out_size) {
    const float* x      = (const float*)d_in[0];
    const float* weight = (const float*)d_in[1];
    float* out          = (float*)d_out;

    const int rows = in_sizes[0] / L_DENSE;   // 131072

    precompute_frag<<<NSTEPS, 128>>>(weight);
    gemm_hmma<<<(rows + MTILE - 1) / MTILE, THREADS>>>(x, out, rows);
}

// round 15
// speedup vs baseline: 1.4616x; 1.2838x over previous
#include <cuda_runtime.h>
#include <cuda_fp16.h>
#include <cstdint>
#include <math.h>

#define L_DENSE 1024
#define LT      64
#define NSTEPS  64        // K / 16
#define MTILE   128       // rows per CTA (8 warps x 16)
#define THREADS 256
#define STAGES  5         // per-warp A ring: 5 x 1KB

// Banded-compressed B: per ks only tiles j(ks), j(ks)+1 are nonzero (fp16-exact).
// g_Bc[ks*32+lane] = { h2 W[na][k0..k0+1], h2 W[na][k0+2..k0+3],
//                      h2 W[nb][k0..],     h2 W[nb][k0+2..] }
// na = 8*j(ks) + lane/4, nb = na+8, k0 = 16ks + (lane%4)*4 (permuted k layout).
__device__ uint4 g_Bc[NSTEPS * 32];
__device__ int   g_j[NSTEPS];

static __device__ __forceinline__ uint32_t f2_h2(float lo, float hi) {
    uint32_t u;
    asm("cvt.rn.f16x2.f32 %0, %1, %2;" : "=r"(u) : "f"(hi), "f"(lo));
    return u;
}

__global__ void precompute_banded(const float* __restrict__ weight) {
    int ks   = blockIdx.x;      // 0..63
    int lane = threadIdx.x;     // 0..31
    __shared__ int jsh;
    if (lane == 0) {
        // first n whose Gaussian overlaps chunk [16ks+1, 16ks+16] (|d|<=43 margin)
        float lo = 16.f * ks + 1.f - 43.f;
        int nmin = 63;
        for (int n = 0; n < LT; ++n)
            if (weight[n] >= lo) { nmin = n; break; }
        int j = nmin >> 3;
        if (j > 6) j = 6;
        g_j[ks] = j;
        jsh = j;
    }
    __syncthreads();
    int j  = jsh;
    int na = 8 * j + (lane >> 2);
    int nb = na + 8;
    int k0 = ks * 16 + (lane & 3) * 4;
    float wa = weight[na], wb = weight[nb];
    uint4 v;
    {
        float d0 = (float)(k0 + 1) - wa, d1 = (float)(k0 + 2) - wa;
        float d2 = (float)(k0 + 3) - wa, d3 = (float)(k0 + 4) - wa;
        v.x = f2_h2(expf(-d0 * d0 * 0.01f), expf(-d1 * d1 * 0.01f));
        v.y = f2_h2(expf(-d2 * d2 * 0.01f), expf(-d3 * d3 * 0.01f));
    }
    {
        float d0 = (float)(k0 + 1) - wb, d1 = (float)(k0 + 2) - wb;
        float d2 = (float)(k0 + 3) - wb, d3 = (float)(k0 + 4) - wb;
        v.z = f2_h2(expf(-d0 * d0 * 0.01f), expf(-d1 * d1 * 0.01f));
        v.w = f2_h2(expf(-d2 * d2 * 0.01f), expf(-d3 * d3 * 0.01f));
    }
    g_Bc[ks * 32 + lane] = v;
}

static __device__ __forceinline__ void mma16816(float c[4],
        uint32_t a0, uint32_t a1, uint32_t a2, uint32_t a3,
        uint32_t b0, uint32_t b1) {
    asm volatile(
        "mma.sync.aligned.m16n8k16.row.col.f32.f16.f16.f32 "
        "{%0,%1,%2,%3}, {%4,%5,%6,%7}, {%8,%9}, {%0,%1,%2,%3};"
        : "+f"(c[0]), "+f"(c[1]), "+f"(c[2]), "+f"(c[3])
        : "r"(a0), "r"(a1), "r"(a2), "r"(a3), "r"(b0), "r"(b1));
}

static __device__ __forceinline__ uint32_t smem_u32(const void* p) {
    uint32_t a;
    asm("{ .reg .u64 t; cvta.to.shared.u64 t, %1; cvt.u32.u64 %0, t; }" : "=r"(a) : "l"(p));
    return a;
}
static __device__ __forceinline__ void cp16(uint32_t saddr, const void* gaddr) {
    asm volatile("cp.async.cg.shared.global [%0], [%1], 16;" :: "r"(saddr), "l"(gaddr));
}
#define CP_COMMIT()  asm volatile("cp.async.commit_group;" ::: "memory")
#define CP_WAIT3()   asm volatile("cp.async.wait_group 3;" ::: "memory")

// dynamic smem layout (bytes):
//   A ring : 8 warps x 5 stages x 1KB = 40960   @ 0
//   Bc     : 64 x 32 x 16B          = 32768   @ 40960
//   js     : 64 x 4B                =   256   @ 73728
#define SM_A   0
#define SM_BC  40960
#define SM_JS  73728
#define SM_TOT 73984

__global__ void __launch_bounds__(THREADS, 3)
gemm_hmma(const float* __restrict__ x, float* __restrict__ out, int rows)
{
    extern __shared__ char smraw[];
    float* SA        = (float*)(smraw + SM_A);
    uint4* Bc        = (uint4*)(smraw + SM_BC);
    int*   js        = (int*)  (smraw + SM_JS);

    const int tid  = threadIdx.x;
    const int warp = tid >> 5;
    const int lane = tid & 31;
    const int wr0  = blockIdx.x * MTILE + warp * 16;   // warp's first row (m16)
    const int rq   = lane >> 2;                        // row within 8-group
    const int kq   = (lane & 3) * 4;                   // permuted k quad base
    const int cc   = (lane & 3) * 2;                   // C column pair

    // ---- copy compressed B + j table into smem ----
    {
        const uint4* g = g_Bc;
        #pragma unroll
        for (int i = tid; i < NSTEPS * 32; i += THREADS) Bc[i] = g[i];
        if (tid < NSTEPS) js[tid] = g_j[tid];
    }

    // Per-warp private A staging (lane reads exactly the chunks it wrote ->
    // per-thread cp.async visibility, no barriers in mainloop).
    const float*   gbase  = x + (size_t)(wr0 + rq) * L_DENSE + kq;
    const uint32_t swbase = smem_u32(SA) + warp * (STAGES * 1024) + lane * 16;

    auto issue_stage = [&](int ks, int slot) {
        uint32_t s = swbase + slot * 1024;
        const float* g = gbase + ks * 16;
        cp16(s,       g);
        cp16(s + 512, g + 8 * L_DENSE);
    };

    #pragma unroll
    for (int s = 0; s < STAGES - 1; ++s) { issue_stage(s, s); CP_COMMIT(); }

    __syncthreads();   // Bc/js visible; does not disturb cp.async groups

    float c_lo[4] = {0.f, 0.f, 0.f, 0.f};
    float c_hi[4] = {0.f, 0.f, 0.f, 0.f};
    int   jcur    = js[0];
    const int r   = wr0 + rq;

    auto store_tile = [&](const float cf[4], int t) {
        if (r < rows) {
            float2 v; v.x = cf[0]; v.y = cf[1];
            __stcs((float2*)(out + (size_t)r * LT + t * 8 + cc), v);
        }
        if (r + 8 < rows) {
            float2 w; w.x = cf[2]; w.y = cf[3];
            __stcs((float2*)(out + (size_t)(r + 8) * LT + t * 8 + cc), w);
        }
    };

    const float* aw0 = SA + warp * (STAGES * 256) + rq * 16 + kq;
    int rslot = 0, wslot = STAGES - 1;

    for (int ks = 0; ks < NSTEPS; ++ks) {
        // sliding accumulator: j increments by exactly 1 (monotone band)
        int jn = js[ks];
        if (jn != jcur) {
            store_tile(c_lo, jcur);
            #pragma unroll
            for (int q = 0; q < 4; ++q) { c_lo[q] = c_hi[q]; c_hi[q] = 0.f; }
            jcur = jn;
        }

        CP_WAIT3();
        if (ks + STAGES - 1 < NSTEPS) issue_stage(ks + STAGES - 1, wslot);
        CP_COMMIT();   // unconditional: keeps wait count aligned at tail

        // A fragment from own-written smem chunks: 2x LDS.128
        const float* ap = aw0 + rslot * 256;
        float4 v0 = *(const float4*)(ap);
        float4 v1 = *(const float4*)(ap + 128);
        uint32_t a0 = f2_h2(v0.x, v0.y);
        uint32_t a2 = f2_h2(v0.z, v0.w);
        uint32_t a1 = f2_h2(v1.x, v1.y);
        uint32_t a3 = f2_h2(v1.z, v1.w);

        // B: one conflict-free LDS.128 (both live tiles)
        uint4 bv = Bc[ks * 32 + lane];
        mma16816(c_lo, a0, a1, a2, a3, bv.x, bv.y);
        mma16816(c_hi, a0, a1, a2, a3, bv.z, bv.w);

        rslot = (rslot + 1 == STAGES) ? 0 : rslot + 1;
        wslot = (wslot + 1 == STAGES) ? 0 : wslot + 1;
    }

    // final: tiles jcur (=6) and jcur+1 (=7)
    store_tile(c_lo, jcur);
    store_tile(c_hi, jcur + 1);
}

extern "C" void kernel_launch(void* const* d_in, const int* in_sizes, int n_in,
                              void* d_out, int out_size) {
    const float* x      = (const float*)d_in[0];
    const float* weight = (const float*)d_in[1];
    float* out          = (float*)d_out;

    const int rows = in_sizes[0] / L_DENSE;   // 131072

    cudaFuncSetAttribute(gemm_hmma, cudaFuncAttributeMaxDynamicSharedMemorySize, SM_TOT);

    precompute_banded<<<NSTEPS, 32>>>(weight);
    gemm_hmma<<<(rows + MTILE - 1) / MTILE, THREADS, SM_TOT>>>(x, out, rows);
}